// round 6
// baseline (speedup 1.0000x reference)
#include <cuda_runtime.h>
#include <cuda_fp16.h>

#define NPIX 49
#define CH 96
#define HD 32
#define HW 56
#define BATCH 128

// Pre-transposed weights: [c][m] so m-adjacent pairs are contiguous
__device__ float g_wq_t[CH * 3 * CH];   // 96 x 288
__device__ float g_wp_t[CH * CH];       // 96 x 96

__global__ void prep_kernel(const float* __restrict__ qkv_w,
                            const float* __restrict__ proj_w) {
    int t = blockIdx.x * blockDim.x + threadIdx.x;
    int stride = gridDim.x * blockDim.x;
    for (int i = t; i < 288 * 96; i += stride) {
        int m = i / 96, c = i % 96;
        g_wq_t[c * 288 + m] = qkv_w[i];
    }
    for (int i = t; i < 96 * 96; i += stride) {
        int m = i / 96, c = i % 96;
        g_wp_t[c * 96 + m] = proj_w[i];
    }
}

// ---- packed f32x2 helpers (dual-FMA on sm_103a; rounding identical to fmaf) ----
typedef unsigned long long u64;

__device__ __forceinline__ void fma2(u64& d, u64 a, u64 b) {
    asm("fma.rn.f32x2 %0, %1, %2, %0;" : "+l"(d) : "l"(a), "l"(b));
}
__device__ __forceinline__ u64 pack2(float lo, float hi) {
    u64 r;
    asm("mov.b64 %0, {%1, %2};" : "=l"(r) : "f"(lo), "f"(hi));
    return r;
}
__device__ __forceinline__ float2 unpack2(u64 v) {
    float2 r;
    asm("mov.b64 {%0, %1}, %2;" : "=f"(r.x), "=f"(r.y) : "l"(v));
    return r;
}

// Fast exp on the FMA pipe (avoids MUFU.EX2 throughput wall).
__device__ __forceinline__ float fexp(float x) {
    x = fmaxf(x, -87.0f);
    float n = rintf(x * 1.4426950408889634f);
    float r = fmaf(n, -0.6931471805599453f, x);
    float p = fmaf(r, 8.3333333e-3f, 4.1666667e-2f);
    p = fmaf(p, r, 0.16666667f);
    p = fmaf(p, r, 0.5f);
    p = fmaf(p, r, 1.0f);
    p = fmaf(p, r, 1.0f);
    int e = (int)n;
    return p * __int_as_float((e + 127) << 23);
}

// Shared memory (floats), liveness-aliased, fp16 qkv:
//  sm_x   : [0, 5376)      xn fp32, 96 rows x stride 56 (7 groups of 8, col7 pad)
//  sm_q16 : [5376, 8064)   q half, 96 rows x stride 56 halfs
//  sm_k16 : [8064, 10752)  k half, 96 rows x stride 56 halfs
//  sm_v16t: [10752, 13104) v half TRANSPOSED, 49 rows x 96 halfs
//  sm_att : [0, 8232)      attn fp32 3*49 rows x stride 56 (aliases x+q16+k16-head; valid after ph2a)
//  sm_av  : [0, 5376)      AV out fp32 (aliases att; written after ph4 read-barrier)
//  sm_mu  : [13104, 13153)  sm_rs : [13153, 13202)  sm_lab : [13202, 13251)
#define SMEM_FLOATS 13252

extern __shared__ float smem[];

__global__ void __launch_bounds__(256, 3)
swin_kernel(const float* __restrict__ x,
            const float* __restrict__ ln_g, const float* __restrict__ ln_b,
            const float* __restrict__ qkv_b,
            const float* __restrict__ proj_b,
            const float* __restrict__ rel_table,
            float* __restrict__ out) {
    float*  sm_x   = smem;
    __half* sm_q16 = (__half*)(smem + 5376);
    __half* sm_k16 = (__half*)(smem + 8064);
    __half* sm_vt  = (__half*)(smem + 10752);
    float*  sm_att = smem;
    float*  sm_av  = smem;
    float*  sm_mu  = smem + 13104;
    float*  sm_rs  = smem + 13153;
    int*    sm_lab = (int*)(smem + 13202);

    const int t  = threadIdx.x;
    const int wid = blockIdx.x;
    const int b  = wid >> 6;
    const int wr = (wid >> 3) & 7;
    const int wc = wid & 7;

    // ---- Phase 0: labels, gather x (roll -3) into padded layout, LN ----
    if (t < NPIX) {
        int pr = t / 7, pc = t % 7;
        int hs = wr * 7 + pr, wsv = wc * 7 + pc;
        int lh = hs < 49 ? 0 : (hs < 53 ? 1 : 2);
        int lw = wsv < 49 ? 0 : (wsv < 53 ? 1 : 2);
        sm_lab[t] = lh * 3 + lw;
    }
    const float* xb = x + (size_t)b * CH * (HW * HW);
    for (int idx = t; idx < CH * NPIX; idx += 256) {
        int c = idx / NPIX, p = idx % NPIX;
        int pr = p / 7, pc = p % 7;
        int gh = wr * 7 + pr + 3; if (gh >= 56) gh -= 56;
        int gw = wc * 7 + pc + 3; if (gw >= 56) gw -= 56;
        sm_x[c * 56 + pr * 8 + pc] = __ldg(xb + c * (HW * HW) + gh * HW + gw);
    }
    __syncthreads();
    if (t < NPIX) {
        int off = (t / 7) * 8 + t % 7;
        float s = 0.f, ss = 0.f;
        #pragma unroll 8
        for (int c = 0; c < CH; ++c) {
            float v = sm_x[c * 56 + off];
            s += v; ss += v * v;
        }
        float mu = s * (1.0f / 96.0f);
        float var = ss * (1.0f / 96.0f) - mu * mu;
        sm_mu[t] = mu;
        sm_rs[t] = rsqrtf(var + 1e-5f);
    }
    __syncthreads();
    for (int idx = t; idx < CH * NPIX; idx += 256) {
        int c = idx / NPIX, p = idx % NPIX;
        int a = c * 56 + (p / 7) * 8 + p % 7;
        sm_x[a] = (sm_x[a] - sm_mu[p]) * sm_rs[p] * __ldg(ln_g + c) + __ldg(ln_b + c);
    }
    __syncthreads();

    // ---- Phase 1: QKV GEMM (288 x 49, K=96), 8m x 7p, fp32; outputs fp16 ----
    if (t < 252) {
        const int mg = t / 7, pg = t % 7;
        const int m0 = mg * 8, p0 = pg * 7;
        u64 acc[4][7];
        #pragma unroll
        for (int a = 0; a < 4; ++a)
            #pragma unroll
            for (int pi = 0; pi < 7; ++pi) acc[a][pi] = 0ull;
        const float* wb = g_wq_t + m0;          // 32B-aligned
        const float* xr0 = sm_x + pg * 8;       // 32B-aligned rows
        #pragma unroll 2
        for (int c = 0; c < CH; ++c) {
            ulonglong2 wa = __ldg((const ulonglong2*)(wb + c * 288));
            ulonglong2 wc2 = __ldg((const ulonglong2*)(wb + c * 288) + 1);
            u64 wp[4] = {wa.x, wa.y, wc2.x, wc2.y};
            float4 xa  = *(const float4*)(xr0 + c * 56);
            float4 xb2 = *(const float4*)(xr0 + c * 56 + 4);
            float xs[7] = {xa.x, xa.y, xa.z, xa.w, xb2.x, xb2.y, xb2.z};
            #pragma unroll
            for (int pi = 0; pi < 7; ++pi) {
                u64 xx = pack2(xs[pi], xs[pi]);
                #pragma unroll
                for (int a = 0; a < 4; ++a)
                    fma2(acc[a][pi], wp[a], xx);
            }
        }
        if (m0 < 192) {
            // q or k: rows [d][i], stride 56 halfs, padded col groups of 8
            __half* dst = (m0 < 96) ? (sm_q16 + m0 * 56) : (sm_k16 + (m0 - 96) * 56);
            #pragma unroll
            for (int a = 0; a < 4; ++a) {
                float b0 = __ldg(qkv_b + m0 + 2 * a);
                float b1 = __ldg(qkv_b + m0 + 2 * a + 1);
                #pragma unroll
                for (int pi = 0; pi < 7; ++pi) {
                    float2 u = unpack2(acc[a][pi]);
                    dst[(2 * a) * 56 + pg * 8 + pi]     = __float2half_rn(u.x + b0);
                    dst[(2 * a + 1) * 56 + pg * 8 + pi] = __float2half_rn(u.y + b1);
                }
            }
        } else {
            // v: transposed store v_t[pixel][m], 8 halfs per pixel (16B aligned)
            const int vm0 = m0 - 192;
            float vb0 = __ldg(qkv_b + m0 + 0), vb1 = __ldg(qkv_b + m0 + 1);
            float vb2 = __ldg(qkv_b + m0 + 2), vb3 = __ldg(qkv_b + m0 + 3);
            float vb4 = __ldg(qkv_b + m0 + 4), vb5 = __ldg(qkv_b + m0 + 5);
            float vb6 = __ldg(qkv_b + m0 + 6), vb7 = __ldg(qkv_b + m0 + 7);
            #pragma unroll
            for (int pi = 0; pi < 7; ++pi) {
                float2 u0 = unpack2(acc[0][pi]);
                float2 u1 = unpack2(acc[1][pi]);
                float2 u2 = unpack2(acc[2][pi]);
                float2 u3 = unpack2(acc[3][pi]);
                __half2* vdst = (__half2*)(sm_vt + (p0 + pi) * 96 + vm0);
                vdst[0] = __floats2half2_rn(u0.x + vb0, u0.y + vb1);
                vdst[1] = __floats2half2_rn(u1.x + vb2, u1.y + vb3);
                vdst[2] = __floats2half2_rn(u2.x + vb4, u2.y + vb5);
                vdst[3] = __floats2half2_rn(u3.x + vb6, u3.y + vb7);
            }
        }
    }
    __syncthreads();

    // ---- Phase 2a: QK^T into registers (fp16 loads, fp32 math) ----
    u64 acc2[3][7];
    float acc6[7];
    int h = 0, ig = 0, jg = 0;
    if (t < 147) {
        h = t / 49;
        int r = t % 49;
        ig = r / 7; jg = r % 7;
        #pragma unroll
        for (int a = 0; a < 3; ++a)
            #pragma unroll
            for (int jj = 0; jj < 7; ++jj) acc2[a][jj] = 0ull;
        #pragma unroll
        for (int jj = 0; jj < 7; ++jj) acc6[jj] = 0.f;
        const __half* qb = sm_q16 + (h * HD) * 56 + ig * 8;
        const __half* kb = sm_k16 + (h * HD) * 56 + jg * 8;
        for (int d = 0; d < HD; ++d) {
            uint4 qraw = *(const uint4*)(qb + d * 56);   // 8 halfs, 16B aligned
            uint4 kraw = *(const uint4*)(kb + d * 56);
            float2 qf0 = __half22float2(*(__half2*)&qraw.x);
            float2 qf1 = __half22float2(*(__half2*)&qraw.y);
            float2 qf2 = __half22float2(*(__half2*)&qraw.z);
            float2 qf3 = __half22float2(*(__half2*)&qraw.w);
            float2 kf0 = __half22float2(*(__half2*)&kraw.x);
            float2 kf1 = __half22float2(*(__half2*)&kraw.y);
            float2 kf2 = __half22float2(*(__half2*)&kraw.z);
            float2 kf3 = __half22float2(*(__half2*)&kraw.w);
            u64 qp[3] = {pack2(qf0.x, qf0.y), pack2(qf1.x, qf1.y), pack2(qf2.x, qf2.y)};
            float q6 = qf3.x;
            float kv[7] = {kf0.x, kf0.y, kf1.x, kf1.y, kf2.x, kf2.y, kf3.x};
            #pragma unroll
            for (int jj = 0; jj < 7; ++jj) {
                u64 kk = pack2(kv[jj], kv[jj]);
                #pragma unroll
                for (int a = 0; a < 3; ++a) fma2(acc2[a][jj], qp[a], kk);
                acc6[jj] = fmaf(q6, kv[jj], acc6[jj]);
            }
        }
    }
    __syncthreads();   // x, q, k dead -> attn may overwrite [0, 8232)

    // ---- Phase 2b: scale + rel bias + shift mask -> attn (stride 56) ----
    if (t < 147) {
        const int i0 = ig * 7, j0 = jg * 7;
        const float scale = 0.17677669529663687f;  // 1/sqrt(32)
        #pragma unroll
        for (int ii = 0; ii < 7; ++ii) {
            int i = i0 + ii;
            int li = sm_lab[i];
            #pragma unroll
            for (int jj = 0; jj < 7; ++jj) {
                int j = j0 + jj;
                float val;
                if (ii == 6) val = acc6[jj];
                else {
                    float2 u = unpack2(acc2[ii >> 1][jj]);
                    val = (ii & 1) ? u.y : u.x;
                }
                int idx = (ig - jg + 6) * 13 + (ii - jj + 6);
                float bias = __ldg(rel_table + idx * 3 + h);
                float msk = (li == sm_lab[j]) ? 0.f : -100.f;
                sm_att[(h * 49 + i) * 56 + j] = fmaf(val, scale, bias + msk);
            }
        }
    }
    __syncthreads();

    // ---- Phase 3: softmax over j (vectorized float4) ----
    if (t < 147) {
        float* row = sm_att + t * 56;                  // 16B aligned (t*224)
        float4 v[12];
        #pragma unroll
        for (int g = 0; g < 12; ++g) v[g] = *(float4*)(row + 4 * g);
        float last = row[48];
        float mx = last;
        #pragma unroll
        for (int g = 0; g < 12; ++g) {
            mx = fmaxf(mx, fmaxf(fmaxf(v[g].x, v[g].y), fmaxf(v[g].z, v[g].w)));
        }
        float s = 0.f;
        #pragma unroll
        for (int g = 0; g < 12; ++g) {
            v[g].x = fexp(v[g].x - mx); v[g].y = fexp(v[g].y - mx);
            v[g].z = fexp(v[g].z - mx); v[g].w = fexp(v[g].w - mx);
            s += (v[g].x + v[g].y) + (v[g].z + v[g].w);
        }
        last = fexp(last - mx); s += last;
        float inv = 1.0f / s;
        #pragma unroll
        for (int g = 0; g < 12; ++g) {
            v[g].x *= inv; v[g].y *= inv; v[g].z *= inv; v[g].w *= inv;
            *(float4*)(row + 4 * g) = v[g];
        }
        row[48] = last * inv;
    }
    __syncthreads();

    // ---- Phase 4: AV (96 x 49, K=49), v fp16 transposed; acc in regs ----
    u64 acc4[2][7];
    if (t < 168) {
        const int mg = t / 7, pg = t % 7;
        const int m0 = mg * 4, p0 = pg * 7;
        const int hh = m0 >> 5;
        #pragma unroll
        for (int a = 0; a < 2; ++a)
            #pragma unroll
            for (int pi = 0; pi < 7; ++pi) acc4[a][pi] = 0ull;
        const __half* vb = sm_vt + m0;
        const float* ab = sm_att + (hh * 49 + p0) * 56;
        for (int j = 0; j < 49; ++j) {
            uint2 vraw = *(const uint2*)(vb + j * 96);   // 4 halfs, 8B aligned
            float2 f0 = __half22float2(*(__half2*)&vraw.x);
            float2 f1 = __half22float2(*(__half2*)&vraw.y);
            u64 vp0 = pack2(f0.x, f0.y);
            u64 vp1 = pack2(f1.x, f1.y);
            #pragma unroll
            for (int pi = 0; pi < 7; ++pi) {
                float av = ab[pi * 56 + j];
                u64 ap = pack2(av, av);
                fma2(acc4[0][pi], vp0, ap);
                fma2(acc4[1][pi], vp1, ap);
            }
        }
    }
    __syncthreads();   // all attn reads done -> av may overwrite [0, 5376)
    if (t < 168) {
        const int mg = t / 7, pg = t % 7;
        const int m0 = mg * 4;
        #pragma unroll
        for (int a = 0; a < 2; ++a)
            #pragma unroll
            for (int pi = 0; pi < 7; ++pi) {
                float2 u = unpack2(acc4[a][pi]);
                sm_av[(m0 + 2 * a) * 56 + pg * 8 + pi]     = u.x;
                sm_av[(m0 + 2 * a + 1) * 56 + pg * 8 + pi] = u.y;
            }
    }
    __syncthreads();

    // ---- Phase 5: proj GEMM (96 x 49, K=96) + scatter (roll +3) ----
    if (t < 168) {
        const int mg = t / 7, pg = t % 7;
        const int m0 = mg * 4, p0 = pg * 7;
        u64 acc[2][7];
        #pragma unroll
        for (int a = 0; a < 2; ++a)
            #pragma unroll
            for (int pi = 0; pi < 7; ++pi) acc[a][pi] = 0ull;
        const float* wb = g_wp_t + m0;          // 16B aligned
        const float* xr0 = sm_av + pg * 8;      // 32B aligned rows
        #pragma unroll 4
        for (int c = 0; c < CH; ++c) {
            ulonglong2 wa = __ldg((const ulonglong2*)(wb + c * 96));
            u64 wp[2] = {wa.x, wa.y};
            float4 xa  = *(const float4*)(xr0 + c * 56);
            float4 xb2 = *(const float4*)(xr0 + c * 56 + 4);
            float xs[7] = {xa.x, xa.y, xa.z, xa.w, xb2.x, xb2.y, xb2.z};
            #pragma unroll
            for (int pi = 0; pi < 7; ++pi) {
                u64 xx = pack2(xs[pi], xs[pi]);
                fma2(acc[0][pi], wp[0], xx);
                fma2(acc[1][pi], wp[1], xx);
            }
        }
        float* ob = out + (size_t)b * CH * (HW * HW);
        int gh = wr * 7 + pg + 3; if (gh >= 56) gh -= 56;
        #pragma unroll
        for (int a = 0; a < 2; ++a) {
            float b0 = __ldg(proj_b + m0 + 2 * a);
            float b1 = __ldg(proj_b + m0 + 2 * a + 1);
            float* orow0 = ob + (m0 + 2 * a) * (HW * HW) + gh * HW;
            float* orow1 = ob + (m0 + 2 * a + 1) * (HW * HW) + gh * HW;
            #pragma unroll
            for (int pi = 0; pi < 7; ++pi) {
                int gw = wc * 7 + pi + 3; if (gw >= 56) gw -= 56;
                float2 u = unpack2(acc[a][pi]);
                orow0[gw] = u.x + b0;
                orow1[gw] = u.y + b1;
            }
        }
    }
}

extern "C" void kernel_launch(void* const* d_in, const int* in_sizes, int n_in,
                              void* d_out, int out_size) {
    const float* x      = (const float*)d_in[0];
    const float* ln_g   = (const float*)d_in[1];
    const float* ln_b   = (const float*)d_in[2];
    const float* qkv_w  = (const float*)d_in[3];
    const float* qkv_b  = (const float*)d_in[4];
    const float* proj_w = (const float*)d_in[5];
    const float* proj_b = (const float*)d_in[6];
    const float* rel    = (const float*)d_in[7];
    float* out = (float*)d_out;

    cudaFuncSetAttribute(swin_kernel, cudaFuncAttributeMaxDynamicSharedMemorySize,
                         SMEM_FLOATS * (int)sizeof(float));

    prep_kernel<<<64, 256>>>(qkv_w, proj_w);
    swin_kernel<<<BATCH * 64, 256, SMEM_FLOATS * sizeof(float)>>>(
        x, ln_g, ln_b, qkv_b, proj_b, rel, out);
}

// round 8
// speedup vs baseline: 1.0202x; 1.0202x over previous
#include <cuda_runtime.h>
#include <cuda_fp16.h>

#define NPIX 49
#define CH 96
#define HD 32
#define HW 56
#define BATCH 128

// Pre-transposed weights: [c][m] so m-adjacent pairs are contiguous
__device__ float g_wq_t[CH * 3 * CH];   // 96 x 288
__device__ float g_wp_t[CH * CH];       // 96 x 96

__global__ void prep_kernel(const float* __restrict__ qkv_w,
                            const float* __restrict__ proj_w) {
    int t = blockIdx.x * blockDim.x + threadIdx.x;
    int stride = gridDim.x * blockDim.x;
    for (int i = t; i < 288 * 96; i += stride) {
        int m = i / 96, c = i % 96;
        g_wq_t[c * 288 + m] = qkv_w[i];
    }
    for (int i = t; i < 96 * 96; i += stride) {
        int m = i / 96, c = i % 96;
        g_wp_t[c * 96 + m] = proj_w[i];
    }
}

// ---- packed f32x2 helpers (dual-FMA on sm_103a; rounding identical to fmaf) ----
typedef unsigned long long u64;

__device__ __forceinline__ void fma2(u64& d, u64 a, u64 b) {
    asm("fma.rn.f32x2 %0, %1, %2, %0;" : "+l"(d) : "l"(a), "l"(b));
}
__device__ __forceinline__ u64 pack2(float lo, float hi) {
    u64 r;
    asm("mov.b64 %0, {%1, %2};" : "=l"(r) : "f"(lo), "f"(hi));
    return r;
}
__device__ __forceinline__ float2 unpack2(u64 v) {
    float2 r;
    asm("mov.b64 {%0, %1}, %2;" : "=f"(r.x), "=f"(r.y) : "l"(v));
    return r;
}

// Fast exp on the FMA pipe (avoids MUFU.EX2 throughput wall).
__device__ __forceinline__ float fexp(float x) {
    x = fmaxf(x, -87.0f);
    float n = rintf(x * 1.4426950408889634f);
    float r = fmaf(n, -0.6931471805599453f, x);
    float p = fmaf(r, 8.3333333e-3f, 4.1666667e-2f);
    p = fmaf(p, r, 0.16666667f);
    p = fmaf(p, r, 0.5f);
    p = fmaf(p, r, 1.0f);
    p = fmaf(p, r, 1.0f);
    int e = (int)n;
    return p * __int_as_float((e + 127) << 23);
}

// Shared memory (floats), liveness-aliased; ONLY v is fp16 (vector stores):
//  sm_k   : [0, 4704)       k fp32 rows [d][i];  after ph4: AV output (stride 49)
//  sm_q   : [4704, 9408)    q fp32 rows [d][i]
//  sm_x   : [9408, 14112)   xn fp32 (96x49)
//  sm_vt  : [14112, 16464)  v fp16 TRANSPOSED [pixel][m], 49 x 96 halfs
//  attn   : [4704, 11907)   3*49*49 fp32, aliases q+x (both dead after ph2a)
//  sm_av  : [0, 4704)       aliases k (dead after ph2a) — disjoint from attn!
//  sm_mu  : [16464,16513)  sm_rs : [16513,16562)  sm_lab : [16562,16611)
#define SMEM_FLOATS 16624

extern __shared__ float smem[];

__global__ void __launch_bounds__(256, 3)
swin_kernel(const float* __restrict__ x,
            const float* __restrict__ ln_g, const float* __restrict__ ln_b,
            const float* __restrict__ qkv_b,
            const float* __restrict__ proj_b,
            const float* __restrict__ rel_table,
            float* __restrict__ out) {
    float*  sm_k   = smem;
    float*  sm_q   = smem + 4704;
    float*  sm_x   = smem + 9408;
    __half* sm_vt  = (__half*)(smem + 14112);
    float*  sm_att = smem + 4704;
    float*  sm_av  = smem;
    float*  sm_mu  = smem + 16464;
    float*  sm_rs  = smem + 16513;
    int*    sm_lab = (int*)(smem + 16562);

    const int t  = threadIdx.x;
    const int wid = blockIdx.x;
    const int b  = wid >> 6;
    const int wr = (wid >> 3) & 7;
    const int wc = wid & 7;

    // ---- Phase 0: labels, gather x (roll -3), LN ----
    if (t < NPIX) {
        int pr = t / 7, pc = t % 7;
        int hs = wr * 7 + pr, wsv = wc * 7 + pc;
        int lh = hs < 49 ? 0 : (hs < 53 ? 1 : 2);
        int lw = wsv < 49 ? 0 : (wsv < 53 ? 1 : 2);
        sm_lab[t] = lh * 3 + lw;
    }
    const float* xb = x + (size_t)b * CH * (HW * HW);
    for (int idx = t; idx < CH * NPIX; idx += 256) {
        int c = idx / NPIX, p = idx % NPIX;
        int pr = p / 7, pc = p % 7;
        int gh = wr * 7 + pr + 3; if (gh >= 56) gh -= 56;
        int gw = wc * 7 + pc + 3; if (gw >= 56) gw -= 56;
        sm_x[c * NPIX + p] = __ldg(xb + c * (HW * HW) + gh * HW + gw);
    }
    __syncthreads();
    if (t < NPIX) {
        float s = 0.f, ss = 0.f;
        #pragma unroll 8
        for (int c = 0; c < CH; ++c) {
            float v = sm_x[c * NPIX + t];
            s += v; ss += v * v;
        }
        float mu = s * (1.0f / 96.0f);
        float var = ss * (1.0f / 96.0f) - mu * mu;
        sm_mu[t] = mu;
        sm_rs[t] = rsqrtf(var + 1e-5f);
    }
    __syncthreads();
    for (int idx = t; idx < CH * NPIX; idx += 256) {
        int c = idx / NPIX, p = idx % NPIX;
        int a = c * NPIX + p;
        sm_x[a] = (sm_x[a] - sm_mu[p]) * sm_rs[p] * __ldg(ln_g + c) + __ldg(ln_b + c);
    }
    __syncthreads();

    // ---- Phase 1: QKV GEMM (288 x 49, K=96), 8m x 7p, weights via __ldg ----
    if (t < 252) {
        const int mg = t / 7, pg = t % 7;
        const int m0 = mg * 8, p0 = pg * 7;
        u64 acc[4][7];
        #pragma unroll
        for (int a = 0; a < 4; ++a)
            #pragma unroll
            for (int pi = 0; pi < 7; ++pi) acc[a][pi] = 0ull;
        const float* wb = g_wq_t + m0;          // 32B-aligned
        const float* xr0 = sm_x + p0;
        #pragma unroll 2
        for (int c = 0; c < CH; ++c) {
            ulonglong2 wa = __ldg((const ulonglong2*)(wb + c * 288));
            ulonglong2 wc2 = __ldg((const ulonglong2*)(wb + c * 288) + 1);
            u64 wp[4] = {wa.x, wa.y, wc2.x, wc2.y};
            const float* xr = xr0 + c * NPIX;
            #pragma unroll
            for (int pi = 0; pi < 7; ++pi) {
                float xv = xr[pi];
                u64 xx = pack2(xv, xv);
                #pragma unroll
                for (int a = 0; a < 4; ++a)
                    fma2(acc[a][pi], wp[a], xx);
            }
        }
        if (m0 < 192) {
            float* dst = (m0 < 96) ? (sm_q + m0 * NPIX) : (sm_k + (m0 - 96) * NPIX);
            #pragma unroll
            for (int a = 0; a < 4; ++a) {
                float b0 = __ldg(qkv_b + m0 + 2 * a);
                float b1 = __ldg(qkv_b + m0 + 2 * a + 1);
                #pragma unroll
                for (int pi = 0; pi < 7; ++pi) {
                    float2 u = unpack2(acc[a][pi]);
                    dst[(2 * a) * NPIX + p0 + pi]     = u.x + b0;
                    dst[(2 * a + 1) * NPIX + p0 + pi] = u.y + b1;
                }
            }
        } else {
            // v: transposed fp16 store v_t[pixel][m], 4x half2 per pixel (8B stores)
            const int vm0 = m0 - 192;
            float vb0 = __ldg(qkv_b + m0 + 0), vb1 = __ldg(qkv_b + m0 + 1);
            float vb2 = __ldg(qkv_b + m0 + 2), vb3 = __ldg(qkv_b + m0 + 3);
            float vb4 = __ldg(qkv_b + m0 + 4), vb5 = __ldg(qkv_b + m0 + 5);
            float vb6 = __ldg(qkv_b + m0 + 6), vb7 = __ldg(qkv_b + m0 + 7);
            #pragma unroll
            for (int pi = 0; pi < 7; ++pi) {
                float2 u0 = unpack2(acc[0][pi]);
                float2 u1 = unpack2(acc[1][pi]);
                float2 u2 = unpack2(acc[2][pi]);
                float2 u3 = unpack2(acc[3][pi]);
                __half2* vdst = (__half2*)(sm_vt + (p0 + pi) * 96 + vm0);
                vdst[0] = __floats2half2_rn(u0.x + vb0, u0.y + vb1);
                vdst[1] = __floats2half2_rn(u1.x + vb2, u1.y + vb3);
                vdst[2] = __floats2half2_rn(u2.x + vb4, u2.y + vb5);
                vdst[3] = __floats2half2_rn(u3.x + vb6, u3.y + vb7);
            }
        }
    }
    __syncthreads();

    // ---- Phase 2a: QK^T into registers (fp32, packed over i) ----
    u64 acc2[3][7];
    float acc6[7];
    int h = 0, ig = 0, jg = 0;
    if (t < 147) {
        h = t / 49;
        int r = t % 49;
        ig = r / 7; jg = r % 7;
        const int i0 = ig * 7, j0 = jg * 7;
        #pragma unroll
        for (int a = 0; a < 3; ++a)
            #pragma unroll
            for (int jj = 0; jj < 7; ++jj) acc2[a][jj] = 0ull;
        #pragma unroll
        for (int jj = 0; jj < 7; ++jj) acc6[jj] = 0.f;
        const float* qb = sm_q + (h * HD) * NPIX;
        const float* kb = sm_k + (h * HD) * NPIX;
        for (int d = 0; d < HD; ++d) {
            float qv[7], kv[7];
            #pragma unroll
            for (int k = 0; k < 7; ++k) {
                qv[k] = qb[d * NPIX + i0 + k];
                kv[k] = kb[d * NPIX + j0 + k];
            }
            u64 qp[3];
            #pragma unroll
            for (int a = 0; a < 3; ++a) qp[a] = pack2(qv[2 * a], qv[2 * a + 1]);
            #pragma unroll
            for (int jj = 0; jj < 7; ++jj) {
                u64 kk = pack2(kv[jj], kv[jj]);
                #pragma unroll
                for (int a = 0; a < 3; ++a) fma2(acc2[a][jj], qp[a], kk);
                acc6[jj] = fmaf(qv[6], kv[jj], acc6[jj]);
            }
        }
    }
    __syncthreads();   // q, k, x now dead -> attn may overwrite [4704, 11907)

    // ---- Phase 2b: scale + rel bias + shift mask -> attn ----
    if (t < 147) {
        const int i0 = ig * 7, j0 = jg * 7;
        const float scale = 0.17677669529663687f;  // 1/sqrt(32)
        #pragma unroll
        for (int ii = 0; ii < 7; ++ii) {
            int i = i0 + ii;
            int li = sm_lab[i];
            #pragma unroll
            for (int jj = 0; jj < 7; ++jj) {
                int j = j0 + jj;
                float val;
                if (ii == 6) val = acc6[jj];
                else {
                    float2 u = unpack2(acc2[ii >> 1][jj]);
                    val = (ii & 1) ? u.y : u.x;
                }
                int idx = (ig - jg + 6) * 13 + (ii - jj + 6);
                float bias = __ldg(rel_table + idx * 3 + h);
                float msk = (li == sm_lab[j]) ? 0.f : -100.f;
                sm_att[(h * 49 + i) * 49 + j] = fmaf(val, scale, bias + msk);
            }
        }
    }
    __syncthreads();

    // ---- Phase 3: softmax over j ----
    if (t < 147) {
        float* row = sm_att + t * 49;
        float mx = -1e30f;
        #pragma unroll 7
        for (int j = 0; j < 49; ++j) mx = fmaxf(mx, row[j]);
        float s = 0.f;
        #pragma unroll 7
        for (int j = 0; j < 49; ++j) {
            float e = fexp(row[j] - mx);
            row[j] = e; s += e;
        }
        float inv = 1.0f / s;
        #pragma unroll 7
        for (int j = 0; j < 49; ++j) row[j] *= inv;
    }
    __syncthreads();

    // ---- Phase 4: AV (96 x 49, K=49), v fp16 transposed; av -> dead k region ----
    // (av region [0,4704) disjoint from attn [4704,11907): no extra barrier needed)
    if (t < 168) {
        const int mg = t / 7, pg = t % 7;
        const int m0 = mg * 4, p0 = pg * 7;
        const int hh = m0 >> 5;
        u64 acc[2][7];
        #pragma unroll
        for (int a = 0; a < 2; ++a)
            #pragma unroll
            for (int pi = 0; pi < 7; ++pi) acc[a][pi] = 0ull;
        const __half* vb = sm_vt + m0;
        const float* ab = sm_att + (hh * 49 + p0) * 49;
        for (int j = 0; j < 49; ++j) {
            uint2 vraw = *(const uint2*)(vb + j * 96);   // 4 halfs, 8B aligned
            float2 f0 = __half22float2(*(__half2*)&vraw.x);
            float2 f1 = __half22float2(*(__half2*)&vraw.y);
            u64 vp0 = pack2(f0.x, f0.y);
            u64 vp1 = pack2(f1.x, f1.y);
            #pragma unroll
            for (int pi = 0; pi < 7; ++pi) {
                float av = ab[pi * 49 + j];
                u64 ap = pack2(av, av);
                fma2(acc[0][pi], vp0, ap);
                fma2(acc[1][pi], vp1, ap);
            }
        }
        #pragma unroll
        for (int a = 0; a < 2; ++a)
            #pragma unroll
            for (int pi = 0; pi < 7; ++pi) {
                float2 u = unpack2(acc[a][pi]);
                sm_av[(m0 + 2 * a) * NPIX + p0 + pi]     = u.x;
                sm_av[(m0 + 2 * a + 1) * NPIX + p0 + pi] = u.y;
            }
    }
    __syncthreads();

    // ---- Phase 5: proj GEMM (96 x 49, K=96) + scatter (roll +3) ----
    if (t < 168) {
        const int mg = t / 7, pg = t % 7;
        const int m0 = mg * 4, p0 = pg * 7;
        u64 acc[2][7];
        #pragma unroll
        for (int a = 0; a < 2; ++a)
            #pragma unroll
            for (int pi = 0; pi < 7; ++pi) acc[a][pi] = 0ull;
        const float* wb = g_wp_t + m0;          // 16B-aligned
        const float* xr0 = sm_av + p0;
        #pragma unroll 4
        for (int c = 0; c < CH; ++c) {
            ulonglong2 wa = __ldg((const ulonglong2*)(wb + c * 96));
            u64 wp[2] = {wa.x, wa.y};
            const float* xr = xr0 + c * NPIX;
            #pragma unroll
            for (int pi = 0; pi < 7; ++pi) {
                float xv = xr[pi];
                u64 xx = pack2(xv, xv);
                fma2(acc[0][pi], wp[0], xx);
                fma2(acc[1][pi], wp[1], xx);
            }
        }
        float* ob = out + (size_t)b * CH * (HW * HW);
        int gh = wr * 7 + pg + 3; if (gh >= 56) gh -= 56;
        #pragma unroll
        for (int a = 0; a < 2; ++a) {
            float b0 = __ldg(proj_b + m0 + 2 * a);
            float b1 = __ldg(proj_b + m0 + 2 * a + 1);
            float* orow0 = ob + (m0 + 2 * a) * (HW * HW) + gh * HW;
            float* orow1 = ob + (m0 + 2 * a + 1) * (HW * HW) + gh * HW;
            #pragma unroll
            for (int pi = 0; pi < 7; ++pi) {
                int gw = wc * 7 + pi + 3; if (gw >= 56) gw -= 56;
                float2 u = unpack2(acc[a][pi]);
                orow0[gw] = u.x + b0;
                orow1[gw] = u.y + b1;
            }
        }
    }
}

extern "C" void kernel_launch(void* const* d_in, const int* in_sizes, int n_in,
                              void* d_out, int out_size) {
    const float* x      = (const float*)d_in[0];
    const float* ln_g   = (const float*)d_in[1];
    const float* ln_b   = (const float*)d_in[2];
    const float* qkv_w  = (const float*)d_in[3];
    const float* qkv_b  = (const float*)d_in[4];
    const float* proj_w = (const float*)d_in[5];
    const float* proj_b = (const float*)d_in[6];
    const float* rel    = (const float*)d_in[7];
    float* out = (float*)d_out;

    cudaFuncSetAttribute(swin_kernel, cudaFuncAttributeMaxDynamicSharedMemorySize,
                         SMEM_FLOATS * (int)sizeof(float));

    prep_kernel<<<64, 256>>>(qkv_w, proj_w);
    swin_kernel<<<BATCH * 64, 256, SMEM_FLOATS * sizeof(float)>>>(
        x, ln_g, ln_b, qkv_b, proj_b, rel, out);
}

// round 11
// speedup vs baseline: 1.0667x; 1.0456x over previous
#include <cuda_runtime.h>

#define NPIX 49
#define CH 96
#define HD 32
#define HW 56
#define BATCH 128

// Pre-transposed weights: [c][m] so m-adjacent pairs are contiguous
__device__ float g_wq_t[CH * 3 * CH];   // 96 x 288
__device__ float g_wp_t[CH * CH];       // 96 x 96

__global__ void prep_kernel(const float* __restrict__ qkv_w,
                            const float* __restrict__ proj_w) {
    int t = blockIdx.x * blockDim.x + threadIdx.x;
    int stride = gridDim.x * blockDim.x;
    for (int i = t; i < 288 * 96; i += stride) {
        int m = i / 96, c = i % 96;
        g_wq_t[c * 288 + m] = qkv_w[i];
    }
    for (int i = t; i < 96 * 96; i += stride) {
        int m = i / 96, c = i % 96;
        g_wp_t[c * 96 + m] = proj_w[i];
    }
}

// ---- packed f32x2 helpers (dual-FMA on sm_103a; rounding identical to fmaf) ----
typedef unsigned long long u64;

__device__ __forceinline__ void fma2(u64& d, u64 a, u64 b) {
    asm("fma.rn.f32x2 %0, %1, %2, %0;" : "+l"(d) : "l"(a), "l"(b));
}
__device__ __forceinline__ u64 pack2(float lo, float hi) {
    u64 r;
    asm("mov.b64 %0, {%1, %2};" : "=l"(r) : "f"(lo), "f"(hi));
    return r;
}
__device__ __forceinline__ float2 unpack2(u64 v) {
    float2 r;
    asm("mov.b64 {%0, %1}, %2;" : "=f"(r.x), "=f"(r.y) : "l"(v));
    return r;
}

// Fast exp on the FMA pipe (avoids MUFU.EX2 throughput wall).
__device__ __forceinline__ float fexp(float x) {
    x = fmaxf(x, -87.0f);
    float n = rintf(x * 1.4426950408889634f);
    float r = fmaf(n, -0.6931471805599453f, x);
    float p = fmaf(r, 8.3333333e-3f, 4.1666667e-2f);
    p = fmaf(p, r, 0.16666667f);
    p = fmaf(p, r, 0.5f);
    p = fmaf(p, r, 1.0f);
    p = fmaf(p, r, 1.0f);
    int e = (int)n;
    return p * __int_as_float((e + 127) << 23);
}

// Shared memory (floats), liveness-aliased, all fp32:
//  sm_k   : [0, 4704)       k rows [d][i] stride 49;   after ph4: AV out (stride 49)
//  sm_vt  : [4704, 9604)    v TRANSPOSED [pixel][m], stride 100 (pad vs bank conflicts)
//  sm_q   : [9604, 14308)   q rows [d][i] stride 49
//  sm_x   : [14308, 19012)  xn (96x49)
//  sm_att : [9604, 17248)   3*49 rows x stride 52 (16B-aligned rows); aliases q+x after ph2a
//  sm_av  : [0, 4704)       aliases k — disjoint from att and vt
//  sm_mu  : [19012,19061)  sm_rs : [19061,19110)  sm_lab : [19110,19159)
#define SMEM_FLOATS 19168

extern __shared__ float smem[];

__global__ void __launch_bounds__(256, 3)
swin_kernel(const float* __restrict__ x,
            const float* __restrict__ ln_g, const float* __restrict__ ln_b,
            const float* __restrict__ qkv_b,
            const float* __restrict__ proj_b,
            const float* __restrict__ rel_table,
            float* __restrict__ out) {
    float* sm_k   = smem;
    float* sm_vt  = smem + 4704;
    float* sm_q   = smem + 9604;
    float* sm_x   = smem + 14308;
    float* sm_att = smem + 9604;
    float* sm_av  = smem;
    float* sm_mu  = smem + 19012;
    float* sm_rs  = smem + 19061;
    int*   sm_lab = (int*)(smem + 19110);

    const int t  = threadIdx.x;
    const int wid = blockIdx.x;
    const int b  = wid >> 6;
    const int wr = (wid >> 3) & 7;
    const int wc = wid & 7;

    // ---- Phase 0: labels, gather x (roll -3), LN ----
    if (t < NPIX) {
        int pr = t / 7, pc = t % 7;
        int hs = wr * 7 + pr, wsv = wc * 7 + pc;
        int lh = hs < 49 ? 0 : (hs < 53 ? 1 : 2);
        int lw = wsv < 49 ? 0 : (wsv < 53 ? 1 : 2);
        sm_lab[t] = lh * 3 + lw;
    }
    const float* xb = x + (size_t)b * CH * (HW * HW);
    for (int idx = t; idx < CH * NPIX; idx += 256) {
        int c = idx / NPIX, p = idx % NPIX;
        int pr = p / 7, pc = p % 7;
        int gh = wr * 7 + pr + 3; if (gh >= 56) gh -= 56;
        int gw = wc * 7 + pc + 3; if (gw >= 56) gw -= 56;
        sm_x[c * NPIX + p] = __ldg(xb + c * (HW * HW) + gh * HW + gw);
    }
    __syncthreads();
    if (t < NPIX) {
        float s = 0.f, ss = 0.f;
        #pragma unroll 8
        for (int c = 0; c < CH; ++c) {
            float v = sm_x[c * NPIX + t];
            s += v; ss += v * v;
        }
        float mu = s * (1.0f / 96.0f);
        float var = ss * (1.0f / 96.0f) - mu * mu;
        sm_mu[t] = mu;
        sm_rs[t] = rsqrtf(var + 1e-5f);
    }
    __syncthreads();
    for (int idx = t; idx < CH * NPIX; idx += 256) {
        int c = idx / NPIX, p = idx % NPIX;
        int a = c * NPIX + p;
        sm_x[a] = (sm_x[a] - sm_mu[p]) * sm_rs[p] * __ldg(ln_g + c) + __ldg(ln_b + c);
    }
    __syncthreads();

    // ---- Phase 1: QKV GEMM (288 x 49, K=96), 8m x 7p, weights via __ldg ----
    if (t < 252) {
        const int mg = t / 7, pg = t % 7;
        const int m0 = mg * 8, p0 = pg * 7;
        u64 acc[4][7];
        #pragma unroll
        for (int a = 0; a < 4; ++a)
            #pragma unroll
            for (int pi = 0; pi < 7; ++pi) acc[a][pi] = 0ull;
        const float* wb = g_wq_t + m0;          // 32B-aligned
        const float* xr0 = sm_x + p0;
        #pragma unroll 2
        for (int c = 0; c < CH; ++c) {
            ulonglong2 wa = __ldg((const ulonglong2*)(wb + c * 288));
            ulonglong2 wc2 = __ldg((const ulonglong2*)(wb + c * 288) + 1);
            u64 wp[4] = {wa.x, wa.y, wc2.x, wc2.y};
            const float* xr = xr0 + c * NPIX;
            #pragma unroll
            for (int pi = 0; pi < 7; ++pi) {
                float xv = xr[pi];
                u64 xx = pack2(xv, xv);
                #pragma unroll
                for (int a = 0; a < 4; ++a)
                    fma2(acc[a][pi], wp[a], xx);
            }
        }
        if (m0 < 192) {
            float* dst = (m0 < 96) ? (sm_q + m0 * NPIX) : (sm_k + (m0 - 96) * NPIX);
            #pragma unroll
            for (int a = 0; a < 4; ++a) {
                float b0 = __ldg(qkv_b + m0 + 2 * a);
                float b1 = __ldg(qkv_b + m0 + 2 * a + 1);
                #pragma unroll
                for (int pi = 0; pi < 7; ++pi) {
                    float2 u = unpack2(acc[a][pi]);
                    dst[(2 * a) * NPIX + p0 + pi]     = u.x + b0;
                    dst[(2 * a + 1) * NPIX + p0 + pi] = u.y + b1;
                }
            }
        } else {
            // v: transposed fp32 store v_t[pixel][m], 2x STS.128 per pixel
            const int vm0 = m0 - 192;
            float vb0 = __ldg(qkv_b + m0 + 0), vb1 = __ldg(qkv_b + m0 + 1);
            float vb2 = __ldg(qkv_b + m0 + 2), vb3 = __ldg(qkv_b + m0 + 3);
            float vb4 = __ldg(qkv_b + m0 + 4), vb5 = __ldg(qkv_b + m0 + 5);
            float vb6 = __ldg(qkv_b + m0 + 6), vb7 = __ldg(qkv_b + m0 + 7);
            #pragma unroll
            for (int pi = 0; pi < 7; ++pi) {
                float2 u0 = unpack2(acc[0][pi]);
                float2 u1 = unpack2(acc[1][pi]);
                float2 u2 = unpack2(acc[2][pi]);
                float2 u3 = unpack2(acc[3][pi]);
                float* vdst = sm_vt + (p0 + pi) * 100 + vm0;   // 16B aligned
                *(float4*)(vdst)     = make_float4(u0.x + vb0, u0.y + vb1, u1.x + vb2, u1.y + vb3);
                *(float4*)(vdst + 4) = make_float4(u2.x + vb4, u2.y + vb5, u3.x + vb6, u3.y + vb7);
            }
        }
    }
    __syncthreads();

    // ---- Phase 2a: QK^T into registers (168 threads: 21 groups x 8 lanes) ----
    u64 acc2[3][7];
    float acc6[7];
    int h = 0, ig = 0, l = 0;
    if (t < 168) {
        int g = t >> 3;
        l = t & 7;             // 0..6 = jg, 7 = helper lane (reductions only)
        h = g / 7;
        ig = g % 7;
        #pragma unroll
        for (int a = 0; a < 3; ++a)
            #pragma unroll
            for (int jj = 0; jj < 7; ++jj) acc2[a][jj] = 0ull;
        #pragma unroll
        for (int jj = 0; jj < 7; ++jj) acc6[jj] = 0.f;
        if (l < 7) {
            const int i0 = ig * 7, j0 = l * 7;
            const float* qb = sm_q + (h * HD) * NPIX;
            const float* kb = sm_k + (h * HD) * NPIX;
            for (int d = 0; d < HD; ++d) {
                float qv[7], kv[7];
                #pragma unroll
                for (int k = 0; k < 7; ++k) {
                    qv[k] = qb[d * NPIX + i0 + k];
                    kv[k] = kb[d * NPIX + j0 + k];
                }
                u64 qp[3];
                #pragma unroll
                for (int a = 0; a < 3; ++a) qp[a] = pack2(qv[2 * a], qv[2 * a + 1]);
                #pragma unroll
                for (int jj = 0; jj < 7; ++jj) {
                    u64 kk = pack2(kv[jj], kv[jj]);
                    #pragma unroll
                    for (int a = 0; a < 3; ++a) fma2(acc2[a][jj], qp[a], kk);
                    acc6[jj] = fmaf(qv[6], kv[jj], acc6[jj]);
                }
            }
        }
    }
    __syncthreads();   // q, k, x dead -> attn may overwrite [9604, 17248)

    // ---- Phase 2b: scale + bias + mask + FUSED softmax (shfl over 8-lane groups) ----
    if (t < 168) {
        const int i0 = ig * 7, j0 = l * 7;
        const float scale = 0.17677669529663687f;  // 1/sqrt(32)
        float s[7][7];
        if (l < 7) {
            #pragma unroll
            for (int jj = 0; jj < 7; ++jj) {
                float2 u0 = unpack2(acc2[0][jj]);
                float2 u1 = unpack2(acc2[1][jj]);
                float2 u2 = unpack2(acc2[2][jj]);
                s[0][jj] = u0.x; s[1][jj] = u0.y;
                s[2][jj] = u1.x; s[3][jj] = u1.y;
                s[4][jj] = u2.x; s[5][jj] = u2.y;
                s[6][jj] = acc6[jj];
            }
            #pragma unroll
            for (int ii = 0; ii < 7; ++ii) {
                int li = sm_lab[i0 + ii];
                #pragma unroll
                for (int jj = 0; jj < 7; ++jj) {
                    int j = j0 + jj;
                    int idx = (ig - l + 6) * 13 + (ii - jj + 6);
                    float bias = __ldg(rel_table + idx * 3 + h);
                    float msk = (li == sm_lab[j]) ? 0.f : -100.f;
                    s[ii][jj] = fmaf(s[ii][jj], scale, bias + msk);
                }
            }
        } else {
            #pragma unroll
            for (int ii = 0; ii < 7; ++ii)
                #pragma unroll
                for (int jj = 0; jj < 7; ++jj) s[ii][jj] = -1e30f;
        }
        const unsigned gm = 0xFFu << (t & 24);   // this thread's 8-lane group
        float inv[7];
        #pragma unroll
        for (int ii = 0; ii < 7; ++ii) {
            float m = s[ii][0];
            #pragma unroll
            for (int jj = 1; jj < 7; ++jj) m = fmaxf(m, s[ii][jj]);
            m = fmaxf(m, __shfl_xor_sync(gm, m, 1));
            m = fmaxf(m, __shfl_xor_sync(gm, m, 2));
            m = fmaxf(m, __shfl_xor_sync(gm, m, 4));
            float ss = 0.f;
            #pragma unroll
            for (int jj = 0; jj < 7; ++jj) {
                s[ii][jj] = fexp(s[ii][jj] - m);
                ss += s[ii][jj];
            }
            ss += __shfl_xor_sync(gm, ss, 1);
            ss += __shfl_xor_sync(gm, ss, 2);
            ss += __shfl_xor_sync(gm, ss, 4);
            inv[ii] = 1.0f / ss;
        }
        if (l < 7) {
            #pragma unroll
            for (int ii = 0; ii < 7; ++ii) {
                float* row = sm_att + (h * 49 + i0 + ii) * 52;
                #pragma unroll
                for (int jj = 0; jj < 7; ++jj)
                    row[j0 + jj] = s[ii][jj] * inv[ii];
            }
        }
    }
    __syncthreads();

    // ---- Phase 4: AV (96 x 49, K=49), float4 attn-rows + float4 v ----
    if (t < 168) {
        const int mg = t / 7, pg = t % 7;
        const int m0 = mg * 4, p0 = pg * 7;
        const int hh = m0 >> 5;
        u64 acc[2][7];
        #pragma unroll
        for (int a = 0; a < 2; ++a)
            #pragma unroll
            for (int pi = 0; pi < 7; ++pi) acc[a][pi] = 0ull;
        const float* ab = sm_att + (hh * 49 + p0) * 52;   // rows 16B aligned
        for (int j4 = 0; j4 < 48; j4 += 4) {
            float4 ar[7];
            #pragma unroll
            for (int pi = 0; pi < 7; ++pi)
                ar[pi] = *(const float4*)(ab + pi * 52 + j4);
            #pragma unroll
            for (int u = 0; u < 4; ++u) {
                float4 vv = *(const float4*)(sm_vt + (j4 + u) * 100 + m0);
                u64 vp0 = pack2(vv.x, vv.y);
                u64 vp1 = pack2(vv.z, vv.w);
                #pragma unroll
                for (int pi = 0; pi < 7; ++pi) {
                    float a = (u == 0) ? ar[pi].x : (u == 1) ? ar[pi].y
                            : (u == 2) ? ar[pi].z : ar[pi].w;
                    u64 ap = pack2(a, a);
                    fma2(acc[0][pi], vp0, ap);
                    fma2(acc[1][pi], vp1, ap);
                }
            }
        }
        {   // j = 48 epilogue
            float4 vv = *(const float4*)(sm_vt + 48 * 100 + m0);
            u64 vp0 = pack2(vv.x, vv.y);
            u64 vp1 = pack2(vv.z, vv.w);
            #pragma unroll
            for (int pi = 0; pi < 7; ++pi) {
                float a = ab[pi * 52 + 48];
                u64 ap = pack2(a, a);
                fma2(acc[0][pi], vp0, ap);
                fma2(acc[1][pi], vp1, ap);
            }
        }
        // av -> dead k region [0,4704): disjoint from att and vt, no barrier needed
        #pragma unroll
        for (int a = 0; a < 2; ++a)
            #pragma unroll
            for (int pi = 0; pi < 7; ++pi) {
                float2 u = unpack2(acc[a][pi]);
                sm_av[(m0 + 2 * a) * NPIX + p0 + pi]     = u.x;
                sm_av[(m0 + 2 * a + 1) * NPIX + p0 + pi] = u.y;
            }
    }
    __syncthreads();

    // ---- Phase 5: proj GEMM (96 x 49, K=96) + scatter (roll +3) ----
    if (t < 168) {
        const int mg = t / 7, pg = t % 7;
        const int m0 = mg * 4, p0 = pg * 7;
        u64 acc[2][7];
        #pragma unroll
        for (int a = 0; a < 2; ++a)
            #pragma unroll
            for (int pi = 0; pi < 7; ++pi) acc[a][pi] = 0ull;
        const float* wb = g_wp_t + m0;          // 16B-aligned
        const float* xr0 = sm_av + p0;
        #pragma unroll 4
        for (int c = 0; c < CH; ++c) {
            ulonglong2 wa = __ldg((const ulonglong2*)(wb + c * 96));
            u64 wp[2] = {wa.x, wa.y};
            const float* xr = xr0 + c * NPIX;
            #pragma unroll
            for (int pi = 0; pi < 7; ++pi) {
                float xv = xr[pi];
                u64 xx = pack2(xv, xv);
                fma2(acc[0][pi], wp[0], xx);
                fma2(acc[1][pi], wp[1], xx);
            }
        }
        float* ob = out + (size_t)b * CH * (HW * HW);
        int gh = wr * 7 + pg + 3; if (gh >= 56) gh -= 56;
        #pragma unroll
        for (int a = 0; a < 2; ++a) {
            float b0 = __ldg(proj_b + m0 + 2 * a);
            float b1 = __ldg(proj_b + m0 + 2 * a + 1);
            float* orow0 = ob + (m0 + 2 * a) * (HW * HW) + gh * HW;
            float* orow1 = ob + (m0 + 2 * a + 1) * (HW * HW) + gh * HW;
            #pragma unroll
            for (int pi = 0; pi < 7; ++pi) {
                int gw = wc * 7 + pi + 3; if (gw >= 56) gw -= 56;
                float2 u = unpack2(acc[a][pi]);
                orow0[gw] = u.x + b0;
                orow1[gw] = u.y + b1;
            }
        }
    }
}

extern "C" void kernel_launch(void* const* d_in, const int* in_sizes, int n_in,
                              void* d_out, int out_size) {
    const float* x      = (const float*)d_in[0];
    const float* ln_g   = (const float*)d_in[1];
    const float* ln_b   = (const float*)d_in[2];
    const float* qkv_w  = (const float*)d_in[3];
    const float* qkv_b  = (const float*)d_in[4];
    const float* proj_w = (const float*)d_in[5];
    const float* proj_b = (const float*)d_in[6];
    const float* rel    = (const float*)d_in[7];
    float* out = (float*)d_out;

    cudaFuncSetAttribute(swin_kernel, cudaFuncAttributeMaxDynamicSharedMemorySize,
                         SMEM_FLOATS * (int)sizeof(float));

    prep_kernel<<<64, 256>>>(qkv_w, proj_w);
    swin_kernel<<<BATCH * 64, 256, SMEM_FLOATS * sizeof(float)>>>(
        x, ln_g, ln_b, qkv_b, proj_b, rel, out);
}

// round 12
// speedup vs baseline: 1.0805x; 1.0129x over previous
#include <cuda_runtime.h>

#define NPIX 49
#define CH 96
#define HD 32
#define HW 56
#define BATCH 128

// Pre-transposed weights: [c][m] so m-adjacent pairs are contiguous
__device__ float g_wq_t[CH * 3 * CH];   // 96 x 288
__device__ float g_wp_t[CH * CH];       // 96 x 96

__global__ void prep_kernel(const float* __restrict__ qkv_w,
                            const float* __restrict__ proj_w) {
    int t = blockIdx.x * blockDim.x + threadIdx.x;
    int stride = gridDim.x * blockDim.x;
    for (int i = t; i < 288 * 96; i += stride) {
        int m = i / 96, c = i % 96;
        g_wq_t[c * 288 + m] = qkv_w[i];
    }
    for (int i = t; i < 96 * 96; i += stride) {
        int m = i / 96, c = i % 96;
        g_wp_t[c * 96 + m] = proj_w[i];
    }
}

// ---- packed f32x2 helpers (dual-FMA on sm_103a; rounding identical to fmaf) ----
typedef unsigned long long u64;

__device__ __forceinline__ void fma2(u64& d, u64 a, u64 b) {
    asm("fma.rn.f32x2 %0, %1, %2, %0;" : "+l"(d) : "l"(a), "l"(b));
}
__device__ __forceinline__ u64 pack2(float lo, float hi) {
    u64 r;
    asm("mov.b64 %0, {%1, %2};" : "=l"(r) : "f"(lo), "f"(hi));
    return r;
}
__device__ __forceinline__ float2 unpack2(u64 v) {
    float2 r;
    asm("mov.b64 {%0, %1}, %2;" : "=f"(r.x), "=f"(r.y) : "l"(v));
    return r;
}

// Fast exp on the FMA pipe (avoids MUFU.EX2 throughput wall).
__device__ __forceinline__ float fexp(float x) {
    x = fmaxf(x, -87.0f);
    float n = rintf(x * 1.4426950408889634f);
    float r = fmaf(n, -0.6931471805599453f, x);
    float p = fmaf(r, 8.3333333e-3f, 4.1666667e-2f);
    p = fmaf(p, r, 0.16666667f);
    p = fmaf(p, r, 0.5f);
    p = fmaf(p, r, 1.0f);
    p = fmaf(p, r, 1.0f);
    int e = (int)n;
    return p * __int_as_float((e + 127) << 23);
}

// Shared memory (floats), liveness-aliased, all fp32:
//  sm_x   : [0, 4704)       xn (96x49)
//  sm_q   : [4704, 9408)    q rows [d][i] stride 49
//  sm_k   : [9408, 14112)   k rows [d][i] stride 49
//  sm_vt  : [14112, 19012)  v TRANSPOSED [pixel][m], stride 100 (16B-aligned rows)
//  sm_att : [0, 7644)       3*49 rows x stride 52 (16B-aligned); aliases x+q after ph2a
//  sm_av  : [9408, 14112)   aliases k (dead after ph2a) — disjoint from att and vt
//  sm_mu  : [19012,19061)  sm_rs : [19061,19110)  sm_lab : [19110,19159)
#define SMEM_FLOATS 19168

extern __shared__ float smem[];

__global__ void __launch_bounds__(256, 3)
swin_kernel(const float* __restrict__ x,
            const float* __restrict__ ln_g, const float* __restrict__ ln_b,
            const float* __restrict__ qkv_b,
            const float* __restrict__ proj_b,
            const float* __restrict__ rel_table,
            float* __restrict__ out) {
    float* sm_x   = smem;
    float* sm_q   = smem + 4704;
    float* sm_k   = smem + 9408;
    float* sm_vt  = smem + 14112;
    float* sm_att = smem;            // valid after phase-2a barrier
    float* sm_av  = smem + 9408;     // aliases k
    float* sm_mu  = smem + 19012;
    float* sm_rs  = smem + 19061;
    int*   sm_lab = (int*)(smem + 19110);

    const int t  = threadIdx.x;
    const int wid = blockIdx.x;
    const int b  = wid >> 6;
    const int wr = (wid >> 3) & 7;
    const int wc = wid & 7;

    // ---- Phase 0: labels, gather x (roll -3), LN ----
    if (t < NPIX) {
        int pr = t / 7, pc = t % 7;
        int hs = wr * 7 + pr, wsv = wc * 7 + pc;
        int lh = hs < 49 ? 0 : (hs < 53 ? 1 : 2);
        int lw = wsv < 49 ? 0 : (wsv < 53 ? 1 : 2);
        sm_lab[t] = lh * 3 + lw;
    }
    const float* xb = x + (size_t)b * CH * (HW * HW);
    for (int idx = t; idx < CH * NPIX; idx += 256) {
        int c = idx / NPIX, p = idx % NPIX;
        int pr = p / 7, pc = p % 7;
        int gh = wr * 7 + pr + 3; if (gh >= 56) gh -= 56;
        int gw = wc * 7 + pc + 3; if (gw >= 56) gw -= 56;
        sm_x[c * NPIX + p] = __ldg(xb + c * (HW * HW) + gh * HW + gw);
    }
    __syncthreads();
    if (t < NPIX) {
        float s = 0.f, ss = 0.f;
        #pragma unroll 8
        for (int c = 0; c < CH; ++c) {
            float v = sm_x[c * NPIX + t];
            s += v; ss += v * v;
        }
        float mu = s * (1.0f / 96.0f);
        float var = ss * (1.0f / 96.0f) - mu * mu;
        sm_mu[t] = mu;
        sm_rs[t] = rsqrtf(var + 1e-5f);
    }
    __syncthreads();
    for (int idx = t; idx < CH * NPIX; idx += 256) {
        int c = idx / NPIX, p = idx % NPIX;
        int a = c * NPIX + p;
        sm_x[a] = (sm_x[a] - sm_mu[p]) * sm_rs[p] * __ldg(ln_g + c) + __ldg(ln_b + c);
    }
    __syncthreads();

    // ---- Phase 1: QKV GEMM (288 x 49, K=96), 8m x 7p, weights via __ldg ----
    if (t < 252) {
        const int mg = t / 7, pg = t % 7;
        const int m0 = mg * 8, p0 = pg * 7;
        u64 acc[4][7];
        #pragma unroll
        for (int a = 0; a < 4; ++a)
            #pragma unroll
            for (int pi = 0; pi < 7; ++pi) acc[a][pi] = 0ull;
        const float* wb = g_wq_t + m0;          // 32B-aligned
        const float* xr0 = sm_x + p0;
        #pragma unroll 2
        for (int c = 0; c < CH; ++c) {
            ulonglong2 wa = __ldg((const ulonglong2*)(wb + c * 288));
            ulonglong2 wc2 = __ldg((const ulonglong2*)(wb + c * 288) + 1);
            u64 wp[4] = {wa.x, wa.y, wc2.x, wc2.y};
            const float* xr = xr0 + c * NPIX;
            #pragma unroll
            for (int pi = 0; pi < 7; ++pi) {
                float xv = xr[pi];
                u64 xx = pack2(xv, xv);
                #pragma unroll
                for (int a = 0; a < 4; ++a)
                    fma2(acc[a][pi], wp[a], xx);
            }
        }
        if (m0 < 192) {
            float* dst = (m0 < 96) ? (sm_q + m0 * NPIX) : (sm_k + (m0 - 96) * NPIX);
            #pragma unroll
            for (int a = 0; a < 4; ++a) {
                float b0 = __ldg(qkv_b + m0 + 2 * a);
                float b1 = __ldg(qkv_b + m0 + 2 * a + 1);
                #pragma unroll
                for (int pi = 0; pi < 7; ++pi) {
                    float2 u = unpack2(acc[a][pi]);
                    dst[(2 * a) * NPIX + p0 + pi]     = u.x + b0;
                    dst[(2 * a + 1) * NPIX + p0 + pi] = u.y + b1;
                }
            }
        } else {
            // v: transposed fp32 store v_t[pixel][m], 2x STS.128 per pixel
            const int vm0 = m0 - 192;
            float vb0 = __ldg(qkv_b + m0 + 0), vb1 = __ldg(qkv_b + m0 + 1);
            float vb2 = __ldg(qkv_b + m0 + 2), vb3 = __ldg(qkv_b + m0 + 3);
            float vb4 = __ldg(qkv_b + m0 + 4), vb5 = __ldg(qkv_b + m0 + 5);
            float vb6 = __ldg(qkv_b + m0 + 6), vb7 = __ldg(qkv_b + m0 + 7);
            #pragma unroll
            for (int pi = 0; pi < 7; ++pi) {
                float2 u0 = unpack2(acc[0][pi]);
                float2 u1 = unpack2(acc[1][pi]);
                float2 u2 = unpack2(acc[2][pi]);
                float2 u3 = unpack2(acc[3][pi]);
                float* vdst = sm_vt + (p0 + pi) * 100 + vm0;   // 16B aligned
                *(float4*)(vdst)     = make_float4(u0.x + vb0, u0.y + vb1, u1.x + vb2, u1.y + vb3);
                *(float4*)(vdst + 4) = make_float4(u2.x + vb4, u2.y + vb5, u3.x + vb6, u3.y + vb7);
            }
        }
    }
    __syncthreads();

    // ---- Phase 2a: QK^T into registers (147 threads, fp32, packed over i) ----
    u64 acc2[3][7];
    float acc6[7];
    int h = 0, ig = 0, jg = 0;
    if (t < 147) {
        h = t / 49;
        int r = t % 49;
        ig = r / 7; jg = r % 7;
        const int i0 = ig * 7, j0 = jg * 7;
        #pragma unroll
        for (int a = 0; a < 3; ++a)
            #pragma unroll
            for (int jj = 0; jj < 7; ++jj) acc2[a][jj] = 0ull;
        #pragma unroll
        for (int jj = 0; jj < 7; ++jj) acc6[jj] = 0.f;
        const float* qb = sm_q + (h * HD) * NPIX;
        const float* kb = sm_k + (h * HD) * NPIX;
        for (int d = 0; d < HD; ++d) {
            float qv[7], kv[7];
            #pragma unroll
            for (int k = 0; k < 7; ++k) {
                qv[k] = qb[d * NPIX + i0 + k];
                kv[k] = kb[d * NPIX + j0 + k];
            }
            u64 qp[3];
            #pragma unroll
            for (int a = 0; a < 3; ++a) qp[a] = pack2(qv[2 * a], qv[2 * a + 1]);
            #pragma unroll
            for (int jj = 0; jj < 7; ++jj) {
                u64 kk = pack2(kv[jj], kv[jj]);
                #pragma unroll
                for (int a = 0; a < 3; ++a) fma2(acc2[a][jj], qp[a], kk);
                acc6[jj] = fmaf(qv[6], kv[jj], acc6[jj]);
            }
        }
    }
    __syncthreads();   // q, k, x dead -> attn may overwrite [0, 7644)

    // ---- Phase 2b: scale + rel bias + shift mask -> attn (stride 52) ----
    if (t < 147) {
        const int i0 = ig * 7, j0 = jg * 7;
        const float scale = 0.17677669529663687f;  // 1/sqrt(32)
        #pragma unroll
        for (int ii = 0; ii < 7; ++ii) {
            int i = i0 + ii;
            int li = sm_lab[i];
            #pragma unroll
            for (int jj = 0; jj < 7; ++jj) {
                int j = j0 + jj;
                float val;
                if (ii == 6) val = acc6[jj];
                else {
                    float2 u = unpack2(acc2[ii >> 1][jj]);
                    val = (ii & 1) ? u.y : u.x;
                }
                int idx = (ig - jg + 6) * 13 + (ii - jj + 6);
                float bias = __ldg(rel_table + idx * 3 + h);
                float msk = (li == sm_lab[j]) ? 0.f : -100.f;
                sm_att[(h * 49 + i) * 52 + j] = fmaf(val, scale, bias + msk);
            }
        }
    }
    __syncthreads();

    // ---- Phase 3: softmax over j (147 rows, float4 vectorized) ----
    if (t < 147) {
        float* row = sm_att + t * 52;                // 16B-aligned (t*208)
        float4 v[12];
        #pragma unroll
        for (int g = 0; g < 12; ++g) v[g] = *(float4*)(row + 4 * g);
        float last = row[48];
        float mx = last;
        #pragma unroll
        for (int g = 0; g < 12; ++g)
            mx = fmaxf(mx, fmaxf(fmaxf(v[g].x, v[g].y), fmaxf(v[g].z, v[g].w)));
        float s = 0.f;
        #pragma unroll
        for (int g = 0; g < 12; ++g) {
            v[g].x = fexp(v[g].x - mx); v[g].y = fexp(v[g].y - mx);
            v[g].z = fexp(v[g].z - mx); v[g].w = fexp(v[g].w - mx);
            s += (v[g].x + v[g].y) + (v[g].z + v[g].w);
        }
        last = fexp(last - mx); s += last;
        float inv = 1.0f / s;
        #pragma unroll
        for (int g = 0; g < 12; ++g) {
            v[g].x *= inv; v[g].y *= inv; v[g].z *= inv; v[g].w *= inv;
            *(float4*)(row + 4 * g) = v[g];
        }
        row[48] = last * inv;
    }
    __syncthreads();

    // ---- Phase 4: AV (96 x 49, K=49), float4 attn-rows + float4 v ----
    if (t < 168) {
        const int mg = t / 7, pg = t % 7;
        const int m0 = mg * 4, p0 = pg * 7;
        const int hh = m0 >> 5;
        u64 acc[2][7];
        #pragma unroll
        for (int a = 0; a < 2; ++a)
            #pragma unroll
            for (int pi = 0; pi < 7; ++pi) acc[a][pi] = 0ull;
        const float* ab = sm_att + (hh * 49 + p0) * 52;   // rows 16B-aligned
        for (int j4 = 0; j4 < 48; j4 += 4) {
            float4 ar[7];
            #pragma unroll
            for (int pi = 0; pi < 7; ++pi)
                ar[pi] = *(const float4*)(ab + pi * 52 + j4);
            #pragma unroll
            for (int u = 0; u < 4; ++u) {
                float4 vv = *(const float4*)(sm_vt + (j4 + u) * 100 + m0);
                u64 vp0 = pack2(vv.x, vv.y);
                u64 vp1 = pack2(vv.z, vv.w);
                #pragma unroll
                for (int pi = 0; pi < 7; ++pi) {
                    float a = (u == 0) ? ar[pi].x : (u == 1) ? ar[pi].y
                            : (u == 2) ? ar[pi].z : ar[pi].w;
                    u64 ap = pack2(a, a);
                    fma2(acc[0][pi], vp0, ap);
                    fma2(acc[1][pi], vp1, ap);
                }
            }
        }
        {   // j = 48 epilogue
            float4 vv = *(const float4*)(sm_vt + 48 * 100 + m0);
            u64 vp0 = pack2(vv.x, vv.y);
            u64 vp1 = pack2(vv.z, vv.w);
            #pragma unroll
            for (int pi = 0; pi < 7; ++pi) {
                float a = ab[pi * 52 + 48];
                u64 ap = pack2(a, a);
                fma2(acc[0][pi], vp0, ap);
                fma2(acc[1][pi], vp1, ap);
            }
        }
        // av -> dead k region [9408,14112): disjoint from att and vt
        #pragma unroll
        for (int a = 0; a < 2; ++a)
            #pragma unroll
            for (int pi = 0; pi < 7; ++pi) {
                float2 u = unpack2(acc[a][pi]);
                sm_av[(m0 + 2 * a) * NPIX + p0 + pi]     = u.x;
                sm_av[(m0 + 2 * a + 1) * NPIX + p0 + pi] = u.y;
            }
    }
    __syncthreads();

    // ---- Phase 5: proj GEMM (96 x 49, K=96) + scatter (roll +3) ----
    if (t < 168) {
        const int mg = t / 7, pg = t % 7;
        const int m0 = mg * 4, p0 = pg * 7;
        u64 acc[2][7];
        #pragma unroll
        for (int a = 0; a < 2; ++a)
            #pragma unroll
            for (int pi = 0; pi < 7; ++pi) acc[a][pi] = 0ull;
        const float* wb = g_wp_t + m0;          // 16B-aligned
        const float* xr0 = sm_av + p0;
        #pragma unroll 4
        for (int c = 0; c < CH; ++c) {
            ulonglong2 wa = __ldg((const ulonglong2*)(wb + c * 96));
            u64 wp[2] = {wa.x, wa.y};
            const float* xr = xr0 + c * NPIX;
            #pragma unroll
            for (int pi = 0; pi < 7; ++pi) {
                float xv = xr[pi];
                u64 xx = pack2(xv, xv);
                fma2(acc[0][pi], wp[0], xx);
                fma2(acc[1][pi], wp[1], xx);
            }
        }
        float* ob = out + (size_t)b * CH * (HW * HW);
        int gh = wr * 7 + pg + 3; if (gh >= 56) gh -= 56;
        #pragma unroll
        for (int a = 0; a < 2; ++a) {
            float b0 = __ldg(proj_b + m0 + 2 * a);
            float b1 = __ldg(proj_b + m0 + 2 * a + 1);
            float* orow0 = ob + (m0 + 2 * a) * (HW * HW) + gh * HW;
            float* orow1 = ob + (m0 + 2 * a + 1) * (HW * HW) + gh * HW;
            #pragma unroll
            for (int pi = 0; pi < 7; ++pi) {
                int gw = wc * 7 + pi + 3; if (gw >= 56) gw -= 56;
                float2 u = unpack2(acc[a][pi]);
                orow0[gw] = u.x + b0;
                orow1[gw] = u.y + b1;
            }
        }
    }
}

extern "C" void kernel_launch(void* const* d_in, const int* in_sizes, int n_in,
                              void* d_out, int out_size) {
    const float* x      = (const float*)d_in[0];
    const float* ln_g   = (const float*)d_in[1];
    const float* ln_b   = (const float*)d_in[2];
    const float* qkv_w  = (const float*)d_in[3];
    const float* qkv_b  = (const float*)d_in[4];
    const float* proj_w = (const float*)d_in[5];
    const float* proj_b = (const float*)d_in[6];
    const float* rel    = (const float*)d_in[7];
    float* out = (float*)d_out;

    cudaFuncSetAttribute(swin_kernel, cudaFuncAttributeMaxDynamicSharedMemorySize,
                         SMEM_FLOATS * (int)sizeof(float));

    prep_kernel<<<64, 256>>>(qkv_w, proj_w);
    swin_kernel<<<BATCH * 64, 256, SMEM_FLOATS * sizeof(float)>>>(
        x, ln_g, ln_b, qkv_b, proj_b, rel, out);
}